// round 2
// baseline (speedup 1.0000x reference)
#include <cuda_runtime.h>

// ---------------------------------------------------------------------------
// GCN: h1 = norm-agg(x @ W1) + b1; relu; h2 = norm-agg(h1 @ W2) + b2;
// out = per-graph mean pool.  N=50000 nodes, E=600000 edges, 64 graphs.
// edge_index / batch are int32 (JAX x64 disabled downcasts int64 -> int32).
// Strategy: CSR (by dst) built per call -> gather-based aggregation (no float
// atomics in edge hot path), fp32 register-tiled GEMMs, pooling fused into
// the second aggregation.
// ---------------------------------------------------------------------------

#define NN 50000
#define NE 600000
#define NG 64
#define C_IN  128
#define C_HID 128
#define C_OUT 64

#define CHUNK  200           // scan chunk
#define NCHUNK 250           // 250 * 200 == 50000 exactly

// ------------------------- static device scratch ---------------------------
__device__ int   g_deg[NN];
__device__ float g_dinv[NN];
__device__ int   g_rowstart[NN + 1];
__device__ int   g_cursor[NN];
__device__ int   g_bsum[NCHUNK];
__device__ int   g_boff[NCHUNK];
__device__ __align__(16) int   g_csr_src[NE];
__device__ __align__(16) float g_csr_w[NE];
__device__ __align__(16) float g_h1[(size_t)NN * C_HID];   // x @ W1
__device__ __align__(16) float g_g1[(size_t)NN * C_HID];   // relu(agg(h1)+b1)
__device__ __align__(16) float g_h2[(size_t)NN * C_OUT];   // g1 @ W2
__device__ __align__(16) float g_pool[NG * C_OUT];

// ------------------------------- helpers -----------------------------------
__device__ __forceinline__ int lower_bound_i32(const int* __restrict__ a,
                                               int n, int v) {
    int lo = 0, hi = n;
    while (lo < hi) {
        int mid = (lo + hi) >> 1;
        if (a[mid] < v) lo = mid + 1; else hi = mid;
    }
    return lo;
}

// ------------------------------- kernels -----------------------------------

// zero degree histogram + pool accumulators
__global__ void k_init() {
    int i = blockIdx.x * blockDim.x + threadIdx.x;
    if (i < NN) g_deg[i] = 0;
    if (i < NG * C_OUT) g_pool[i] = 0.0f;
}

// degree of dst side (edges only; +1 self-loop applied in dinv)
__global__ void k_deg(const int* __restrict__ ei) {
    int e = blockIdx.x * blockDim.x + threadIdx.x;
    if (e < NE) {
        int d = ei[NE + e];
        atomicAdd(&g_deg[d], 1);
    }
}

__global__ void k_dinv() {
    int i = blockIdx.x * blockDim.x + threadIdx.x;
    if (i < NN) g_dinv[i] = rsqrtf((float)(g_deg[i] + 1));
}

// exclusive scan of g_deg into g_rowstart: pass A (per-chunk)
__global__ void k_scanA() {
    __shared__ int s[256];
    int t = threadIdx.x;
    int idx = blockIdx.x * CHUNK + t;
    int v = (t < CHUNK) ? g_deg[idx] : 0;
    s[t] = v;
    __syncthreads();
    #pragma unroll
    for (int off = 1; off < 256; off <<= 1) {
        int add = (t >= off) ? s[t - off] : 0;
        __syncthreads();
        s[t] += add;
        __syncthreads();
    }
    if (t < CHUNK) g_rowstart[idx] = s[t] - v;   // exclusive within chunk
    if (t == 255) g_bsum[blockIdx.x] = s[255];
}

// pass B: scan chunk totals
__global__ void k_scanB() {
    __shared__ int s[256];
    int t = threadIdx.x;
    int v = (t < NCHUNK) ? g_bsum[t] : 0;
    s[t] = v;
    __syncthreads();
    #pragma unroll
    for (int off = 1; off < 256; off <<= 1) {
        int add = (t >= off) ? s[t - off] : 0;
        __syncthreads();
        s[t] += add;
        __syncthreads();
    }
    if (t < NCHUNK) g_boff[t] = s[t] - v;        // exclusive
}

// pass C: add chunk offsets, init cursors, cap rowstart
__global__ void k_scanC() {
    int i = blockIdx.x * blockDim.x + threadIdx.x;
    if (i < NN) {
        int r = g_rowstart[i] + g_boff[i / CHUNK];
        g_rowstart[i] = r;
        g_cursor[i]   = r;
    }
    if (i == 0) g_rowstart[NN] = NE;
}

// fill CSR: slot per edge under its dst row; precompute norm weight
__global__ void k_fill(const int* __restrict__ ei) {
    int e = blockIdx.x * blockDim.x + threadIdx.x;
    if (e < NE) {
        int s = ei[e];
        int d = ei[NE + e];
        int pos = atomicAdd(&g_cursor[d], 1);
        g_csr_src[pos] = s;
        g_csr_w[pos]   = g_dinv[s] * g_dinv[d];
    }
}

// ---------------- fp32 GEMM: C[M,BN] = A[M,128] @ W[128,BN] -----------------
// BM=128, BK=16, per-thread 8x8 microtile. TH = (128/8)*(BN/8).
template<int BN, int TH>
__global__ void __launch_bounds__(TH)
k_gemm128(const float* __restrict__ A, const float* __restrict__ W,
          float* __restrict__ C, int M) {
    __shared__ float As[16][132];      // k-major (transposed)
    __shared__ float Ws[16][BN];
    const int tid  = threadIdx.x;
    const int row0 = blockIdx.x * 128;
    const int rg   = tid / (BN / 8);   // 0..15
    const int cg   = tid % (BN / 8);

    float acc[8][8];
    #pragma unroll
    for (int i = 0; i < 8; i++)
        #pragma unroll
        for (int j = 0; j < 8; j++) acc[i][j] = 0.0f;

    for (int k0 = 0; k0 < 128; k0 += 16) {
        // A tile: 128 rows x 16 k, store transposed
        for (int f = tid; f < 128 * 4; f += TH) {
            int r  = f >> 2;
            int k4 = (f & 3) * 4;
            float4 v = make_float4(0.f, 0.f, 0.f, 0.f);
            int gr = row0 + r;
            if (gr < M) v = *(const float4*)(A + (size_t)gr * 128 + k0 + k4);
            As[k4 + 0][r] = v.x; As[k4 + 1][r] = v.y;
            As[k4 + 2][r] = v.z; As[k4 + 3][r] = v.w;
        }
        // W tile: 16 rows x BN
        for (int f = tid; f < 16 * (BN / 4); f += TH) {
            int k  = f / (BN / 4);
            int n4 = (f % (BN / 4)) * 4;
            *(float4*)&Ws[k][n4] = *(const float4*)(W + (size_t)(k0 + k) * BN + n4);
        }
        __syncthreads();
        #pragma unroll
        for (int kk = 0; kk < 16; kk++) {
            float a[8], b[8];
            *(float4*)&a[0] = *(const float4*)&As[kk][rg * 8];
            *(float4*)&a[4] = *(const float4*)&As[kk][rg * 8 + 4];
            *(float4*)&b[0] = *(const float4*)&Ws[kk][cg * 8];
            *(float4*)&b[4] = *(const float4*)&Ws[kk][cg * 8 + 4];
            #pragma unroll
            for (int i = 0; i < 8; i++)
                #pragma unroll
                for (int j = 0; j < 8; j++)
                    acc[i][j] += a[i] * b[j];
        }
        __syncthreads();
    }
    #pragma unroll
    for (int i = 0; i < 8; i++) {
        int gr = row0 + rg * 8 + i;
        if (gr < M) {
            *(float4*)(C + (size_t)gr * BN + cg * 8)     =
                make_float4(acc[i][0], acc[i][1], acc[i][2], acc[i][3]);
            *(float4*)(C + (size_t)gr * BN + cg * 8 + 4) =
                make_float4(acc[i][4], acc[i][5], acc[i][6], acc[i][7]);
        }
    }
}

// --------------- aggregation, C=128: one warp per dst node -----------------
// out[i] = relu( sum_e w_e * h[src_e] + dinv[i]^2 * h[i] + bias )
__global__ void k_agg128(const float* __restrict__ h,
                         const float* __restrict__ bias,
                         float* __restrict__ out) {
    int warp = (blockIdx.x * blockDim.x + threadIdx.x) >> 5;
    if (warp >= NN) return;
    int lane = threadIdx.x & 31;
    const float4* hv = (const float4*)h;   // 32 float4 per row

    int   beg = g_rowstart[warp];
    int   end = g_rowstart[warp + 1];
    float di  = g_dinv[warp];
    float ws  = di * di;

    float4 self = hv[(size_t)warp * 32 + lane];
    float4 acc  = make_float4(self.x * ws, self.y * ws, self.z * ws, self.w * ws);

    int e = beg;
    for (; e + 1 < end; e += 2) {
        int   s0 = g_csr_src[e];     int   s1 = g_csr_src[e + 1];
        float w0 = g_csr_w[e];       float w1 = g_csr_w[e + 1];
        float4 v0 = hv[(size_t)s0 * 32 + lane];
        float4 v1 = hv[(size_t)s1 * 32 + lane];
        acc.x += v0.x * w0 + v1.x * w1;
        acc.y += v0.y * w0 + v1.y * w1;
        acc.z += v0.z * w0 + v1.z * w1;
        acc.w += v0.w * w0 + v1.w * w1;
    }
    if (e < end) {
        int s0 = g_csr_src[e]; float w0 = g_csr_w[e];
        float4 v0 = hv[(size_t)s0 * 32 + lane];
        acc.x += v0.x * w0; acc.y += v0.y * w0;
        acc.z += v0.z * w0; acc.w += v0.w * w0;
    }
    float4 bb = ((const float4*)bias)[lane];
    acc.x = fmaxf(acc.x + bb.x, 0.f);
    acc.y = fmaxf(acc.y + bb.y, 0.f);
    acc.z = fmaxf(acc.z + bb.z, 0.f);
    acc.w = fmaxf(acc.w + bb.w, 0.f);
    ((float4*)out)[(size_t)warp * 32 + lane] = acc;
}

// ------- aggregation C=64 + bias + fused mean-pool accumulation ------------
__global__ void k_agg64_pool(const float* __restrict__ h,
                             const float* __restrict__ bias,
                             const int* __restrict__ batch) {
    int warp = (blockIdx.x * blockDim.x + threadIdx.x) >> 5;
    if (warp >= NN) return;
    int lane = threadIdx.x & 31;
    const float2* hv = (const float2*)h;   // 32 float2 per row

    int   beg = g_rowstart[warp];
    int   end = g_rowstart[warp + 1];
    float di  = g_dinv[warp];
    float ws  = di * di;

    float2 self = hv[(size_t)warp * 32 + lane];
    float2 acc  = make_float2(self.x * ws, self.y * ws);

    int e = beg;
    for (; e + 1 < end; e += 2) {
        int   s0 = g_csr_src[e];     int   s1 = g_csr_src[e + 1];
        float w0 = g_csr_w[e];       float w1 = g_csr_w[e + 1];
        float2 v0 = hv[(size_t)s0 * 32 + lane];
        float2 v1 = hv[(size_t)s1 * 32 + lane];
        acc.x += v0.x * w0 + v1.x * w1;
        acc.y += v0.y * w0 + v1.y * w1;
    }
    if (e < end) {
        int s0 = g_csr_src[e]; float w0 = g_csr_w[e];
        float2 v0 = hv[(size_t)s0 * 32 + lane];
        acc.x += v0.x * w0; acc.y += v0.y * w0;
    }
    float2 bb = ((const float2*)bias)[lane];
    acc.x += bb.x;
    acc.y += bb.y;

    int g = batch[warp];
    atomicAdd(&g_pool[g * C_OUT + lane * 2],     acc.x);
    atomicAdd(&g_pool[g * C_OUT + lane * 2 + 1], acc.y);
}

// final: divide pooled sums by per-graph node counts (binary search on batch)
__global__ void k_final(const int* __restrict__ batch,
                        float* __restrict__ out) {
    int idx = blockIdx.x * blockDim.x + threadIdx.x;
    if (idx >= NG * C_OUT) return;
    int g = idx >> 6;
    int lo = lower_bound_i32(batch, NN, g);
    int hi = lower_bound_i32(batch, NN, g + 1);
    float cnt = (float)(hi - lo);
    out[idx] = g_pool[idx] / fmaxf(cnt, 1.0f);
}

// ------------------------------ launch -------------------------------------
extern "C" void kernel_launch(void* const* d_in, const int* in_sizes, int n_in,
                              void* d_out, int out_size) {
    const float* x     = (const float*)d_in[0];
    const float* W1    = (const float*)d_in[1];
    const float* b1    = (const float*)d_in[2];
    const float* W2    = (const float*)d_in[3];
    const float* b2    = (const float*)d_in[4];
    const int*   ei    = (const int*)d_in[5];
    const int*   batch = (const int*)d_in[6];
    float* out = (float*)d_out;

    // resolve __device__ symbol addresses
    float *h1, *g1, *h2;
    cudaGetSymbolAddress((void**)&h1, g_h1);
    cudaGetSymbolAddress((void**)&g1, g_g1);
    cudaGetSymbolAddress((void**)&h2, g_h2);

    const int TB = 256;
    const int gN  = (NN + TB - 1) / TB;   // 196
    const int gE  = (NE + TB - 1) / TB;   // 2344
    const int gM  = (NN + 127) / 128;     // 391 GEMM row-tiles
    const int gAg = (NN + 7) / 8;         // 6250 (8 warps/block)

    k_init<<<gN, TB>>>();
    k_deg<<<gE, TB>>>(ei);
    k_dinv<<<gN, TB>>>();
    k_scanA<<<NCHUNK, 256>>>();
    k_scanB<<<1, 256>>>();
    k_scanC<<<gN, TB>>>();
    k_fill<<<gE, TB>>>(ei);

    k_gemm128<128, 256><<<gM, 256>>>(x, W1, h1, NN);
    k_agg128<<<gAg, TB>>>(h1, b1, g1);
    k_gemm128<64, 128><<<gM, 128>>>(g1, W2, h2, NN);
    k_agg64_pool<<<gAg, TB>>>(h2, b2, batch);
    k_final<<<(NG * C_OUT + TB - 1) / TB, TB>>>(batch, out);
}

// round 3
// speedup vs baseline: 1.3002x; 1.3002x over previous
#include <cuda_runtime.h>

// ---------------------------------------------------------------------------
// GCN: h1 = norm-agg(x @ W1) + b1; relu; h2 = norm-agg(h1 @ W2) + b2;
// out = per-graph mean pool.  N=50000 nodes, E=600000 edges, 64 graphs.
// edge_index / batch are int32. CSR built per call; gather-based aggregation;
// GEMMs on tensor cores (mma.sync m16n8k8 tf32, rna-rounded inputs).
// ---------------------------------------------------------------------------

#define NN 50000
#define NE 600000
#define NG 64
#define C_IN  128
#define C_HID 128
#define C_OUT 64

#define CHUNK  200           // scan chunk
#define NCHUNK 250           // 250 * 200 == 50000 exactly

// ------------------------- static device scratch ---------------------------
__device__ int   g_deg[NN];
__device__ float g_dinv[NN];
__device__ int   g_rowstart[NN + 1];
__device__ int   g_cursor[NN];
__device__ int   g_bsum[NCHUNK];
__device__ int   g_boff[NCHUNK];
__device__ __align__(16) int   g_csr_src[NE];
__device__ __align__(16) float g_csr_w[NE];
__device__ __align__(16) float g_h1[(size_t)NN * C_HID];   // x @ W1
__device__ __align__(16) float g_g1[(size_t)NN * C_HID];   // relu(agg(h1)+b1)
__device__ __align__(16) float g_h2[(size_t)NN * C_OUT];   // g1 @ W2
__device__ __align__(16) float g_pool[NG * C_OUT];

// ------------------------------- helpers -----------------------------------
__device__ __forceinline__ int lower_bound_i32(const int* __restrict__ a,
                                               int n, int v) {
    int lo = 0, hi = n;
    while (lo < hi) {
        int mid = (lo + hi) >> 1;
        if (a[mid] < v) lo = mid + 1; else hi = mid;
    }
    return lo;
}

__device__ __forceinline__ unsigned f2tf32(float f) {
    unsigned u;
    asm("cvt.rna.tf32.f32 %0, %1;" : "=r"(u) : "f"(f));
    return u;
}

__device__ __forceinline__ void mma_tf32(float* c, const unsigned* a,
                                         const unsigned* b) {
    asm volatile(
        "mma.sync.aligned.m16n8k8.row.col.f32.tf32.tf32.f32 "
        "{%0,%1,%2,%3}, {%4,%5,%6,%7}, {%8,%9}, {%0,%1,%2,%3};\n"
        : "+f"(c[0]), "+f"(c[1]), "+f"(c[2]), "+f"(c[3])
        : "r"(a[0]), "r"(a[1]), "r"(a[2]), "r"(a[3]), "r"(b[0]), "r"(b[1]));
}

// ------------------------------- kernels -----------------------------------

// zero degree histogram + pool accumulators
__global__ void k_init() {
    int i = blockIdx.x * blockDim.x + threadIdx.x;
    if (i < NN) g_deg[i] = 0;
    if (i < NG * C_OUT) g_pool[i] = 0.0f;
}

// degree of dst side (edges only; +1 self-loop applied in dinv)
__global__ void k_deg(const int* __restrict__ ei) {
    int e = blockIdx.x * blockDim.x + threadIdx.x;
    if (e < NE) {
        int d = ei[NE + e];
        atomicAdd(&g_deg[d], 1);
    }
}

// exclusive scan of g_deg into g_rowstart (pass A) + dinv computation
__global__ void k_scanA() {
    __shared__ int s[256];
    int t = threadIdx.x;
    int idx = blockIdx.x * CHUNK + t;
    int v = (t < CHUNK) ? g_deg[idx] : 0;
    if (t < CHUNK) g_dinv[idx] = rsqrtf((float)(v + 1));
    s[t] = v;
    __syncthreads();
    #pragma unroll
    for (int off = 1; off < 256; off <<= 1) {
        int add = (t >= off) ? s[t - off] : 0;
        __syncthreads();
        s[t] += add;
        __syncthreads();
    }
    if (t < CHUNK) g_rowstart[idx] = s[t] - v;   // exclusive within chunk
    if (t == 255) g_bsum[blockIdx.x] = s[255];
}

// pass B: scan chunk totals
__global__ void k_scanB() {
    __shared__ int s[256];
    int t = threadIdx.x;
    int v = (t < NCHUNK) ? g_bsum[t] : 0;
    s[t] = v;
    __syncthreads();
    #pragma unroll
    for (int off = 1; off < 256; off <<= 1) {
        int add = (t >= off) ? s[t - off] : 0;
        __syncthreads();
        s[t] += add;
        __syncthreads();
    }
    if (t < NCHUNK) g_boff[t] = s[t] - v;        // exclusive
}

// pass C: add chunk offsets, init cursors, cap rowstart
__global__ void k_scanC() {
    int i = blockIdx.x * blockDim.x + threadIdx.x;
    if (i < NN) {
        int r = g_rowstart[i] + g_boff[i / CHUNK];
        g_rowstart[i] = r;
        g_cursor[i]   = r;
    }
    if (i == 0) g_rowstart[NN] = NE;
}

// fill CSR: slot per edge under its dst row; precompute norm weight
__global__ void k_fill(const int* __restrict__ ei) {
    int e = blockIdx.x * blockDim.x + threadIdx.x;
    if (e < NE) {
        int s = ei[e];
        int d = ei[NE + e];
        int pos = atomicAdd(&g_cursor[d], 1);
        g_csr_src[pos] = s;
        g_csr_w[pos]   = g_dinv[s] * g_dinv[d];
    }
}

// --------------- tf32 tensor-core GEMM: C[M,BN] = A[M,128] @ W[128,BN] ------
// Block tile 128 x BN, 256 threads = 8 warps laid out 4(m) x 2(n).
// Warp tile 32 x (BN/2). m16n8k8 fragments from K-major smem (stride 20,
// conflict-free: bank = (20*row + k) % 32 hits all 32 banks per warp).
template<int BN>
__global__ void __launch_bounds__(256)
k_gemm_tf32(const float* __restrict__ A, const float* __restrict__ W,
            float* __restrict__ C, int M) {
    constexpr int WN = BN / 2;     // warp n width
    constexpr int NT = WN / 8;     // n-tiles per warp (8 or 4)
    __shared__ float As[128][20];  // rows x k-chunk(16) + pad
    __shared__ float Ws[BN][20];   // cols x k-chunk(16) + pad (B transposed)

    const int tid  = threadIdx.x;
    const int wid  = tid >> 5;
    const int lane = tid & 31;
    const int mw   = wid & 3;       // 0..3  (32 rows each)
    const int nw   = wid >> 2;      // 0..1  (WN cols each)
    const int row0 = blockIdx.x * 128;
    const int qr   = lane >> 2;     // 0..7
    const int qk   = lane & 3;      // 0..3

    float acc[2][NT][4];
    #pragma unroll
    for (int mt = 0; mt < 2; mt++)
        #pragma unroll
        for (int nt = 0; nt < NT; nt++)
            #pragma unroll
            for (int j = 0; j < 4; j++) acc[mt][nt][j] = 0.0f;

    for (int k0 = 0; k0 < 128; k0 += 16) {
        // A tile: 128 rows x 16 k (tf32-rounded), float4 path
        #pragma unroll
        for (int f = tid; f < 512; f += 256) {
            int r  = f >> 2;
            int k4 = (f & 3) * 4;
            float4 v = make_float4(0.f, 0.f, 0.f, 0.f);
            int gr = row0 + r;
            if (gr < M) v = *(const float4*)(A + (size_t)gr * 128 + k0 + k4);
            float4 t;
            t.x = __uint_as_float(f2tf32(v.x));
            t.y = __uint_as_float(f2tf32(v.y));
            t.z = __uint_as_float(f2tf32(v.z));
            t.w = __uint_as_float(f2tf32(v.w));
            *(float4*)&As[r][k4] = t;
        }
        // W tile: transpose-store [n][k]
        #pragma unroll
        for (int f = tid; f < 16 * (BN / 4); f += 256) {
            int k  = f / (BN / 4);
            int n4 = (f % (BN / 4)) * 4;
            float4 v = *(const float4*)(W + (size_t)(k0 + k) * BN + n4);
            Ws[n4 + 0][k] = __uint_as_float(f2tf32(v.x));
            Ws[n4 + 1][k] = __uint_as_float(f2tf32(v.y));
            Ws[n4 + 2][k] = __uint_as_float(f2tf32(v.z));
            Ws[n4 + 3][k] = __uint_as_float(f2tf32(v.w));
        }
        __syncthreads();

        #pragma unroll
        for (int kk = 0; kk < 16; kk += 8) {
            unsigned afr[2][4];
            #pragma unroll
            for (int mt = 0; mt < 2; mt++) {
                int rb = mw * 32 + mt * 16;
                afr[mt][0] = __float_as_uint(As[rb + qr    ][kk + qk    ]);
                afr[mt][1] = __float_as_uint(As[rb + qr + 8][kk + qk    ]);
                afr[mt][2] = __float_as_uint(As[rb + qr    ][kk + qk + 4]);
                afr[mt][3] = __float_as_uint(As[rb + qr + 8][kk + qk + 4]);
            }
            #pragma unroll
            for (int nt = 0; nt < NT; nt++) {
                int nc = nw * WN + nt * 8 + qr;
                unsigned bfr[2];
                bfr[0] = __float_as_uint(Ws[nc][kk + qk    ]);
                bfr[1] = __float_as_uint(Ws[nc][kk + qk + 4]);
                mma_tf32(acc[0][nt], afr[0], bfr);
                mma_tf32(acc[1][nt], afr[1], bfr);
            }
        }
        __syncthreads();
    }

    // epilogue: float2 stores
    #pragma unroll
    for (int mt = 0; mt < 2; mt++) {
        int rb = row0 + mw * 32 + mt * 16 + qr;
        #pragma unroll
        for (int nt = 0; nt < NT; nt++) {
            int col = nw * WN + nt * 8 + 2 * qk;
            if (rb < M)
                *(float2*)(C + (size_t)rb * BN + col) =
                    make_float2(acc[mt][nt][0], acc[mt][nt][1]);
            if (rb + 8 < M)
                *(float2*)(C + (size_t)(rb + 8) * BN + col) =
                    make_float2(acc[mt][nt][2], acc[mt][nt][3]);
        }
    }
}

// --------------- aggregation, C=128: one warp per dst node -----------------
// out[i] = relu( sum_e w_e * h[src_e] + dinv[i]^2 * h[i] + bias )
__global__ void k_agg128(const float* __restrict__ h,
                         const float* __restrict__ bias,
                         float* __restrict__ out) {
    int warp = (blockIdx.x * blockDim.x + threadIdx.x) >> 5;
    if (warp >= NN) return;
    int lane = threadIdx.x & 31;
    const float4* hv = (const float4*)h;   // 32 float4 per row

    int   beg = g_rowstart[warp];
    int   end = g_rowstart[warp + 1];
    float di  = g_dinv[warp];
    float ws  = di * di;

    float4 self = hv[(size_t)warp * 32 + lane];
    float4 acc  = make_float4(self.x * ws, self.y * ws, self.z * ws, self.w * ws);

    int e  = beg;
    int n4 = beg + ((end - beg) & ~3);
    for (; e < n4; e += 4) {
        int   s0 = g_csr_src[e];     int   s1 = g_csr_src[e + 1];
        int   s2 = g_csr_src[e + 2]; int   s3 = g_csr_src[e + 3];
        float w0 = g_csr_w[e];       float w1 = g_csr_w[e + 1];
        float w2 = g_csr_w[e + 2];   float w3 = g_csr_w[e + 3];
        float4 v0 = hv[(size_t)s0 * 32 + lane];
        float4 v1 = hv[(size_t)s1 * 32 + lane];
        float4 v2 = hv[(size_t)s2 * 32 + lane];
        float4 v3 = hv[(size_t)s3 * 32 + lane];
        acc.x += v0.x * w0 + v1.x * w1 + v2.x * w2 + v3.x * w3;
        acc.y += v0.y * w0 + v1.y * w1 + v2.y * w2 + v3.y * w3;
        acc.z += v0.z * w0 + v1.z * w1 + v2.z * w2 + v3.z * w3;
        acc.w += v0.w * w0 + v1.w * w1 + v2.w * w2 + v3.w * w3;
    }
    for (; e < end; e++) {
        int s0 = g_csr_src[e]; float w0 = g_csr_w[e];
        float4 v0 = hv[(size_t)s0 * 32 + lane];
        acc.x += v0.x * w0; acc.y += v0.y * w0;
        acc.z += v0.z * w0; acc.w += v0.w * w0;
    }
    float4 bb = ((const float4*)bias)[lane];
    acc.x = fmaxf(acc.x + bb.x, 0.f);
    acc.y = fmaxf(acc.y + bb.y, 0.f);
    acc.z = fmaxf(acc.z + bb.z, 0.f);
    acc.w = fmaxf(acc.w + bb.w, 0.f);
    ((float4*)out)[(size_t)warp * 32 + lane] = acc;
}

// ------- aggregation C=64 + bias + fused mean-pool accumulation ------------
__global__ void k_agg64_pool(const float* __restrict__ h,
                             const float* __restrict__ bias,
                             const int* __restrict__ batch) {
    int warp = (blockIdx.x * blockDim.x + threadIdx.x) >> 5;
    if (warp >= NN) return;
    int lane = threadIdx.x & 31;
    const float2* hv = (const float2*)h;   // 32 float2 per row

    int   beg = g_rowstart[warp];
    int   end = g_rowstart[warp + 1];
    float di  = g_dinv[warp];
    float ws  = di * di;

    float2 self = hv[(size_t)warp * 32 + lane];
    float2 acc  = make_float2(self.x * ws, self.y * ws);

    int e  = beg;
    int n4 = beg + ((end - beg) & ~3);
    for (; e < n4; e += 4) {
        int   s0 = g_csr_src[e];     int   s1 = g_csr_src[e + 1];
        int   s2 = g_csr_src[e + 2]; int   s3 = g_csr_src[e + 3];
        float w0 = g_csr_w[e];       float w1 = g_csr_w[e + 1];
        float w2 = g_csr_w[e + 2];   float w3 = g_csr_w[e + 3];
        float2 v0 = hv[(size_t)s0 * 32 + lane];
        float2 v1 = hv[(size_t)s1 * 32 + lane];
        float2 v2 = hv[(size_t)s2 * 32 + lane];
        float2 v3 = hv[(size_t)s3 * 32 + lane];
        acc.x += v0.x * w0 + v1.x * w1 + v2.x * w2 + v3.x * w3;
        acc.y += v0.y * w0 + v1.y * w1 + v2.y * w2 + v3.y * w3;
    }
    for (; e < end; e++) {
        int s0 = g_csr_src[e]; float w0 = g_csr_w[e];
        float2 v0 = hv[(size_t)s0 * 32 + lane];
        acc.x += v0.x * w0; acc.y += v0.y * w0;
    }
    float2 bb = ((const float2*)bias)[lane];
    acc.x += bb.x;
    acc.y += bb.y;

    int g = batch[warp];
    atomicAdd(&g_pool[g * C_OUT + lane * 2],     acc.x);
    atomicAdd(&g_pool[g * C_OUT + lane * 2 + 1], acc.y);
}

// final: divide pooled sums by per-graph node counts (binary search on batch)
__global__ void k_final(const int* __restrict__ batch,
                        float* __restrict__ out) {
    int idx = blockIdx.x * blockDim.x + threadIdx.x;
    if (idx >= NG * C_OUT) return;
    int g = idx >> 6;
    int lo = lower_bound_i32(batch, NN, g);
    int hi = lower_bound_i32(batch, NN, g + 1);
    float cnt = (float)(hi - lo);
    out[idx] = g_pool[idx] / fmaxf(cnt, 1.0f);
}

// ------------------------------ launch -------------------------------------
extern "C" void kernel_launch(void* const* d_in, const int* in_sizes, int n_in,
                              void* d_out, int out_size) {
    const float* x     = (const float*)d_in[0];
    const float* W1    = (const float*)d_in[1];
    const float* b1    = (const float*)d_in[2];
    const float* W2    = (const float*)d_in[3];
    const float* b2    = (const float*)d_in[4];
    const int*   ei    = (const int*)d_in[5];
    const int*   batch = (const int*)d_in[6];
    float* out = (float*)d_out;

    float *h1, *g1, *h2;
    cudaGetSymbolAddress((void**)&h1, g_h1);
    cudaGetSymbolAddress((void**)&g1, g_g1);
    cudaGetSymbolAddress((void**)&h2, g_h2);

    const int TB = 256;
    const int gN  = (NN + TB - 1) / TB;   // 196
    const int gE  = (NE + TB - 1) / TB;   // 2344
    const int gM  = (NN + 127) / 128;     // 391 GEMM row-tiles
    const int gAg = (NN + 7) / 8;         // 6250 (8 warps/block)

    k_init<<<gN, TB>>>();
    k_deg<<<gE, TB>>>(ei);
    k_scanA<<<NCHUNK, 256>>>();
    k_scanB<<<1, 256>>>();
    k_scanC<<<gN, TB>>>();
    k_fill<<<gE, TB>>>(ei);

    k_gemm_tf32<128><<<gM, 256>>>(x, W1, h1, NN);
    k_agg128<<<gAg, TB>>>(h1, b1, g1);
    k_gemm_tf32<64><<<gM, 256>>>(g1, W2, h2, NN);
    k_agg64_pool<<<gAg, TB>>>(h2, b2, batch);
    k_final<<<(NG * C_OUT + TB - 1) / TB, TB>>>(batch, out);
}

// round 5
// speedup vs baseline: 1.3610x; 1.0467x over previous
#include <cuda_runtime.h>
#include <cuda_fp16.h>

// ---------------------------------------------------------------------------
// GCN: h1 = norm-agg(x @ W1) + b1; relu; h2 = norm-agg(h1 @ W2) + b2;
// out = per-graph mean pool.  N=50000, E=600000, 64 graphs.
// CSR built per call; gather-based aggregation; tf32 tensor-core GEMMs;
// intermediate features stored fp16 to halve L2 traffic in aggregation.
// ---------------------------------------------------------------------------

#define NN 50000
#define NE 600000
#define NG 64
#define C_IN  128
#define C_HID 128
#define C_OUT 64

#define CHUNK  200           // scan chunk
#define NCHUNK 250           // 250 * 200 == 50000 exactly

// ------------------------- static device scratch ---------------------------
__device__ int   g_deg[NN];
__device__ float g_dinv[NN];
__device__ int   g_rowstart[NN + 1];
__device__ int   g_cursor[NN];
__device__ int   g_bsum[NCHUNK];
__device__ __align__(16) int    g_csr_src[NE];
__device__ __align__(16) float  g_csr_w[NE];
__device__ __align__(16) __half g_h1[(size_t)NN * C_HID];   // x @ W1
__device__ __align__(16) __half g_g1[(size_t)NN * C_HID];   // relu(agg(h1)+b1)
__device__ __align__(16) __half g_h2[(size_t)NN * C_OUT];   // g1 @ W2
__device__ __align__(16) float  g_pool[NG * C_OUT];

// ------------------------------- helpers -----------------------------------
__device__ __forceinline__ int lower_bound_i32(const int* __restrict__ a,
                                               int n, int v) {
    int lo = 0, hi = n;
    while (lo < hi) {
        int mid = (lo + hi) >> 1;
        if (a[mid] < v) lo = mid + 1; else hi = mid;
    }
    return lo;
}

__device__ __forceinline__ unsigned f2tf32(float f) {
    unsigned u;
    asm("cvt.rna.tf32.f32 %0, %1;" : "=r"(u) : "f"(f));
    return u;
}

__device__ __forceinline__ void mma_tf32(float* c, const unsigned* a,
                                         const unsigned* b) {
    asm volatile(
        "mma.sync.aligned.m16n8k8.row.col.f32.tf32.tf32.f32 "
        "{%0,%1,%2,%3}, {%4,%5,%6,%7}, {%8,%9}, {%0,%1,%2,%3};\n"
        : "+f"(c[0]), "+f"(c[1]), "+f"(c[2]), "+f"(c[3])
        : "r"(a[0]), "r"(a[1]), "r"(a[2]), "r"(a[3]), "r"(b[0]), "r"(b[1]));
}

// ------------------------------- kernels -----------------------------------

// degree of dst side (edges only; +1 self-loop applied in dinv)
__global__ void k_deg(const int* __restrict__ ei) {
    int e = blockIdx.x * blockDim.x + threadIdx.x;
    if (e < NE) {
        int d = ei[NE + e];
        atomicAdd(&g_deg[d], 1);
    }
}

// per-chunk exclusive scan of g_deg into g_rowstart + dinv + chunk sums
__global__ void k_scanA() {
    __shared__ int s[256];
    int t = threadIdx.x;
    int idx = blockIdx.x * CHUNK + t;
    int v = (t < CHUNK) ? g_deg[idx] : 0;
    if (t < CHUNK) g_dinv[idx] = rsqrtf((float)(v + 1));
    s[t] = v;
    __syncthreads();
    #pragma unroll
    for (int off = 1; off < 256; off <<= 1) {
        int add = (t >= off) ? s[t - off] : 0;
        __syncthreads();
        s[t] += add;
        __syncthreads();
    }
    if (t < CHUNK) g_rowstart[idx] = s[t] - v;   // exclusive within chunk
    if (t == 255) g_bsum[blockIdx.x] = s[255];
}

// fused pass: every block redundantly scans the 250 chunk sums in smem,
// then applies its offsets, inits cursors, caps rowstart.
__global__ void k_scanC() {
    __shared__ int s[256];
    __shared__ int sbo[NCHUNK];
    int t = threadIdx.x;
    int v = (t < NCHUNK) ? g_bsum[t] : 0;
    s[t] = v;
    __syncthreads();
    #pragma unroll
    for (int off = 1; off < 256; off <<= 1) {
        int add = (t >= off) ? s[t - off] : 0;
        __syncthreads();
        s[t] += add;
        __syncthreads();
    }
    if (t < NCHUNK) sbo[t] = s[t] - v;           // exclusive chunk offsets
    __syncthreads();

    int i = blockIdx.x * blockDim.x + t;
    if (i < NN) {
        int r = g_rowstart[i] + sbo[i / CHUNK];
        g_rowstart[i] = r;
        g_cursor[i]   = r;
    }
    if (i == 0) g_rowstart[NN] = NE;
}

// fill CSR: slot per edge under its dst row; precompute norm weight
__global__ void k_fill(const int* __restrict__ ei) {
    int e = blockIdx.x * blockDim.x + threadIdx.x;
    if (e < NE) {
        int s = ei[e];
        int d = ei[NE + e];
        int pos = atomicAdd(&g_cursor[d], 1);
        g_csr_src[pos] = s;
        g_csr_w[pos]   = g_dinv[s] * g_dinv[d];
    }
}

// ------- tf32 tensor-core GEMM: C[M,BN](fp16) = A[M,128] @ W[128,BN] --------
// Block tile 128 x BN, 256 threads = 8 warps laid out 4(m) x 2(n).
// A may be fp32 (layer 1) or fp16 (layer 2); smem holds tf32-safe fp32.
template<int BN, typename AT>
__global__ void __launch_bounds__(256)
k_gemm_tf32(const AT* __restrict__ A, const float* __restrict__ W,
            __half* __restrict__ C, int M) {
    constexpr int WN = BN / 2;     // warp n width
    constexpr int NT = WN / 8;     // n-tiles per warp
    __shared__ float As[128][20];  // rows x k-chunk(16) + pad
    __shared__ float Ws[BN][20];   // cols x k-chunk(16) + pad (B transposed)

    const int tid  = threadIdx.x;
    const int wid  = tid >> 5;
    const int lane = tid & 31;
    const int mw   = wid & 3;       // 0..3  (32 rows each)
    const int nw   = wid >> 2;      // 0..1  (WN cols each)
    const int row0 = blockIdx.x * 128;
    const int qr   = lane >> 2;     // 0..7
    const int qk   = lane & 3;      // 0..3

    float acc[2][NT][4];
    #pragma unroll
    for (int mt = 0; mt < 2; mt++)
        #pragma unroll
        for (int nt = 0; nt < NT; nt++)
            #pragma unroll
            for (int j = 0; j < 4; j++) acc[mt][nt][j] = 0.0f;

    for (int k0 = 0; k0 < 128; k0 += 16) {
        // A tile: 128 rows x 16 k
        #pragma unroll
        for (int f = tid; f < 512; f += 256) {
            int r  = f >> 2;
            int k4 = (f & 3) * 4;
            int gr = row0 + r;
            float4 t = make_float4(0.f, 0.f, 0.f, 0.f);
            if (gr < M) {
                if constexpr (sizeof(AT) == 4) {
                    float4 v = *(const float4*)((const float*)A +
                                                (size_t)gr * 128 + k0 + k4);
                    t.x = __uint_as_float(f2tf32(v.x));
                    t.y = __uint_as_float(f2tf32(v.y));
                    t.z = __uint_as_float(f2tf32(v.z));
                    t.w = __uint_as_float(f2tf32(v.w));
                } else {
                    const __half2* p = (const __half2*)((const __half*)A +
                                                        (size_t)gr * 128 + k0 + k4);
                    float2 a = __half22float2(p[0]);
                    float2 b = __half22float2(p[1]);
                    t.x = a.x; t.y = a.y; t.z = b.x; t.w = b.y;  // fp16 exact in tf32
                }
            }
            *(float4*)&As[r][k4] = t;
        }
        // W tile: transpose-store [n][k]
        #pragma unroll
        for (int f = tid; f < 16 * (BN / 4); f += 256) {
            int k  = f / (BN / 4);
            int n4 = (f % (BN / 4)) * 4;
            float4 v = *(const float4*)(W + (size_t)(k0 + k) * BN + n4);
            Ws[n4 + 0][k] = __uint_as_float(f2tf32(v.x));
            Ws[n4 + 1][k] = __uint_as_float(f2tf32(v.y));
            Ws[n4 + 2][k] = __uint_as_float(f2tf32(v.z));
            Ws[n4 + 3][k] = __uint_as_float(f2tf32(v.w));
        }
        __syncthreads();

        #pragma unroll
        for (int kk = 0; kk < 16; kk += 8) {
            unsigned afr[2][4];
            #pragma unroll
            for (int mt = 0; mt < 2; mt++) {
                int rb = mw * 32 + mt * 16;
                afr[mt][0] = __float_as_uint(As[rb + qr    ][kk + qk    ]);
                afr[mt][1] = __float_as_uint(As[rb + qr + 8][kk + qk    ]);
                afr[mt][2] = __float_as_uint(As[rb + qr    ][kk + qk + 4]);
                afr[mt][3] = __float_as_uint(As[rb + qr + 8][kk + qk + 4]);
            }
            #pragma unroll
            for (int nt = 0; nt < NT; nt++) {
                int nc = nw * WN + nt * 8 + qr;
                unsigned bfr[2];
                bfr[0] = __float_as_uint(Ws[nc][kk + qk    ]);
                bfr[1] = __float_as_uint(Ws[nc][kk + qk + 4]);
                mma_tf32(acc[0][nt], afr[0], bfr);
                mma_tf32(acc[1][nt], afr[1], bfr);
            }
        }
        __syncthreads();
    }

    // epilogue: fp16 stores (half2)
    #pragma unroll
    for (int mt = 0; mt < 2; mt++) {
        int rb = row0 + mw * 32 + mt * 16 + qr;
        #pragma unroll
        for (int nt = 0; nt < NT; nt++) {
            int col = nw * WN + nt * 8 + 2 * qk;
            if (rb < M)
                *(__half2*)(C + (size_t)rb * BN + col) =
                    __floats2half2_rn(acc[mt][nt][0], acc[mt][nt][1]);
            if (rb + 8 < M)
                *(__half2*)(C + (size_t)(rb + 8) * BN + col) =
                    __floats2half2_rn(acc[mt][nt][2], acc[mt][nt][3]);
        }
    }
}

// --------------- aggregation, C=128: one warp per dst node -----------------
// out[i] = relu( sum_e w_e * h[src_e] + dinv[i]^2 * h[i] + bias )  (fp16 i/o)
__global__ void k_agg128(const __half* __restrict__ h,
                         const float* __restrict__ bias,
                         __half* __restrict__ out) {
    int warp = (blockIdx.x * blockDim.x + threadIdx.x) >> 5;
    if (warp >= NN) return;
    int lane = threadIdx.x & 31;
    const uint2* hv = (const uint2*)h;   // 32 x (4 halves) per row

    int   beg = g_rowstart[warp];
    int   end = g_rowstart[warp + 1];
    float di  = g_dinv[warp];
    float ws  = di * di;

    uint2 su = hv[(size_t)warp * 32 + lane];
    float2 s0f = __half22float2(*(const __half2*)&su.x);
    float2 s1f = __half22float2(*(const __half2*)&su.y);
    float4 acc = make_float4(s0f.x * ws, s0f.y * ws, s1f.x * ws, s1f.y * ws);

    int e  = beg;
    int n4 = beg + ((end - beg) & ~3);
    for (; e < n4; e += 4) {
        int   i0 = g_csr_src[e];     int   i1 = g_csr_src[e + 1];
        int   i2 = g_csr_src[e + 2]; int   i3 = g_csr_src[e + 3];
        float w0 = g_csr_w[e];       float w1 = g_csr_w[e + 1];
        float w2 = g_csr_w[e + 2];   float w3 = g_csr_w[e + 3];
        uint2 u0 = hv[(size_t)i0 * 32 + lane];
        uint2 u1 = hv[(size_t)i1 * 32 + lane];
        uint2 u2 = hv[(size_t)i2 * 32 + lane];
        uint2 u3 = hv[(size_t)i3 * 32 + lane];
        float2 a0 = __half22float2(*(const __half2*)&u0.x);
        float2 b0 = __half22float2(*(const __half2*)&u0.y);
        float2 a1 = __half22float2(*(const __half2*)&u1.x);
        float2 b1 = __half22float2(*(const __half2*)&u1.y);
        float2 a2 = __half22float2(*(const __half2*)&u2.x);
        float2 b2 = __half22float2(*(const __half2*)&u2.y);
        float2 a3 = __half22float2(*(const __half2*)&u3.x);
        float2 b3 = __half22float2(*(const __half2*)&u3.y);
        acc.x += a0.x * w0 + a1.x * w1 + a2.x * w2 + a3.x * w3;
        acc.y += a0.y * w0 + a1.y * w1 + a2.y * w2 + a3.y * w3;
        acc.z += b0.x * w0 + b1.x * w1 + b2.x * w2 + b3.x * w3;
        acc.w += b0.y * w0 + b1.y * w1 + b2.y * w2 + b3.y * w3;
    }
    for (; e < end; e++) {
        int i0 = g_csr_src[e]; float w0 = g_csr_w[e];
        uint2 u0 = hv[(size_t)i0 * 32 + lane];
        float2 a0 = __half22float2(*(const __half2*)&u0.x);
        float2 b0 = __half22float2(*(const __half2*)&u0.y);
        acc.x += a0.x * w0; acc.y += a0.y * w0;
        acc.z += b0.x * w0; acc.w += b0.y * w0;
    }
    float4 bb = ((const float4*)bias)[lane];
    acc.x = fmaxf(acc.x + bb.x, 0.f);
    acc.y = fmaxf(acc.y + bb.y, 0.f);
    acc.z = fmaxf(acc.z + bb.z, 0.f);
    acc.w = fmaxf(acc.w + bb.w, 0.f);
    uint2 ov;
    *(__half2*)&ov.x = __floats2half2_rn(acc.x, acc.y);
    *(__half2*)&ov.y = __floats2half2_rn(acc.z, acc.w);
    ((uint2*)out)[(size_t)warp * 32 + lane] = ov;
}

// ------- aggregation C=64 + bias + fused mean-pool accumulation ------------
__global__ void k_agg64_pool(const __half* __restrict__ h,
                             const float* __restrict__ bias,
                             const int* __restrict__ batch) {
    int warp = (blockIdx.x * blockDim.x + threadIdx.x) >> 5;
    if (warp >= NN) return;
    int lane = threadIdx.x & 31;
    const __half2* hv = (const __half2*)h;   // 32 half2 per row

    int   beg = g_rowstart[warp];
    int   end = g_rowstart[warp + 1];
    float di  = g_dinv[warp];
    float ws  = di * di;

    float2 sf = __half22float2(hv[(size_t)warp * 32 + lane]);
    float2 acc = make_float2(sf.x * ws, sf.y * ws);

    int e  = beg;
    int n4 = beg + ((end - beg) & ~3);
    for (; e < n4; e += 4) {
        int   i0 = g_csr_src[e];     int   i1 = g_csr_src[e + 1];
        int   i2 = g_csr_src[e + 2]; int   i3 = g_csr_src[e + 3];
        float w0 = g_csr_w[e];       float w1 = g_csr_w[e + 1];
        float w2 = g_csr_w[e + 2];   float w3 = g_csr_w[e + 3];
        float2 v0 = __half22float2(hv[(size_t)i0 * 32 + lane]);
        float2 v1 = __half22float2(hv[(size_t)i1 * 32 + lane]);
        float2 v2 = __half22float2(hv[(size_t)i2 * 32 + lane]);
        float2 v3 = __half22float2(hv[(size_t)i3 * 32 + lane]);
        acc.x += v0.x * w0 + v1.x * w1 + v2.x * w2 + v3.x * w3;
        acc.y += v0.y * w0 + v1.y * w1 + v2.y * w2 + v3.y * w3;
    }
    for (; e < end; e++) {
        int i0 = g_csr_src[e]; float w0 = g_csr_w[e];
        float2 v0 = __half22float2(hv[(size_t)i0 * 32 + lane]);
        acc.x += v0.x * w0; acc.y += v0.y * w0;
    }
    float2 bb = ((const float2*)bias)[lane];
    acc.x += bb.x;
    acc.y += bb.y;

    int g = batch[warp];
    atomicAdd(&g_pool[g * C_OUT + lane * 2],     acc.x);
    atomicAdd(&g_pool[g * C_OUT + lane * 2 + 1], acc.y);
}

// final: divide pooled sums by per-graph node counts (binary search on batch)
__global__ void k_final(const int* __restrict__ batch,
                        float* __restrict__ out) {
    int idx = blockIdx.x * blockDim.x + threadIdx.x;
    if (idx >= NG * C_OUT) return;
    int g = idx >> 6;
    int lo = lower_bound_i32(batch, NN, g);
    int hi = lower_bound_i32(batch, NN, g + 1);
    float cnt = (float)(hi - lo);
    out[idx] = g_pool[idx] / fmaxf(cnt, 1.0f);
}

// ------------------------------ launch -------------------------------------
extern "C" void kernel_launch(void* const* d_in, const int* in_sizes, int n_in,
                              void* d_out, int out_size) {
    const float* x     = (const float*)d_in[0];
    const float* W1    = (const float*)d_in[1];
    const float* b1    = (const float*)d_in[2];
    const float* W2    = (const float*)d_in[3];
    const float* b2    = (const float*)d_in[4];
    const int*   ei    = (const int*)d_in[5];
    const int*   batch = (const int*)d_in[6];
    float* out = (float*)d_out;

    __half *h1, *g1, *h2;
    void *degp, *poolp;
    cudaGetSymbolAddress((void**)&h1, g_h1);
    cudaGetSymbolAddress((void**)&g1, g_g1);
    cudaGetSymbolAddress((void**)&h2, g_h2);
    cudaGetSymbolAddress(&degp, g_deg);
    cudaGetSymbolAddress(&poolp, g_pool);

    const int TB = 256;
    const int gN  = (NN + TB - 1) / TB;   // 196
    const int gE  = (NE + TB - 1) / TB;   // 2344
    const int gM  = (NN + 127) / 128;     // 391 GEMM row-tiles
    const int gAg = (NN + 7) / 8;         // 6250 (8 warps/block)

    cudaMemsetAsync(degp, 0, NN * sizeof(int));
    cudaMemsetAsync(poolp, 0, NG * C_OUT * sizeof(float));
    k_deg<<<gE, TB>>>(ei);
    k_scanA<<<NCHUNK, 256>>>();
    k_scanC<<<gN, TB>>>();
    k_fill<<<gE, TB>>>(ei);

    k_gemm_tf32<128, float><<<gM, 256>>>(x, W1, h1, NN);
    k_agg128<<<gAg, TB>>>(h1, b1, g1);
    k_gemm_tf32<64, __half><<<gM, 256>>>(g1, W2, h2, NN);
    k_agg64_pool<<<gAg, TB>>>(h2, b2, batch);
    k_final<<<(NG * C_OUT + TB - 1) / TB, TB>>>(batch, out);
}